// round 2
// baseline (speedup 1.0000x reference)
#include <cuda_runtime.h>
#include <math.h>
#include <stdint.h>

// Problem constants: B=2, T=4096, d_model=1024, H=16, d_head=64, m=64
#define T_SEQ 4096
#define DMODEL 1024
#define NBH    32      // B*H
#define NROWS  8192    // B*T
#define NSWEEP 12

// ---------------- device scratch (no runtime allocation allowed) ----------------
__device__ __align__(16) float g_Q[NROWS * DMODEL];
__device__ __align__(16) float g_K[NROWS * DMODEL];
__device__ __align__(16) float g_V[NROWS * DMODEL];
__device__ __align__(16) float g_attn[NROWS * DMODEL];
__device__ __align__(16) float g_A[NBH * T_SEQ * 64];      // A_hat  [bh][t][mi]
__device__ __align__(16) float g_S[NBH * T_SEQ * 64];      // B raw scores [bh][t][mi]
__device__ __align__(16) float g_Qlm[NBH * 64 * 64];
__device__ __align__(16) float g_Klm[NBH * 64 * 64];
__device__ __align__(16) float g_BV[NBH * 64 * 64];
__device__ __align__(16) float g_CBV[NBH * 64 * 64];
__device__ __align__(16) float g_BVpart[NBH * 8 * 64 * 64];
__device__ float g_cmax[NBH * 64];
__device__ float g_csum[NBH * 64];

// ---------------------------------------------------------------------------
// NT GEMM: C[M,N] = A[M,K] * B[N,K]^T   (row-major). M,N,K multiples of 128/16.
// 128x128 tile, BK=16, 256 threads, 8x8 microtile.
// ---------------------------------------------------------------------------
__global__ __launch_bounds__(256) void gemm_nt_kernel(
    const float* __restrict__ A, const float* __restrict__ B, float* __restrict__ C,
    int M, int N, int K)
{
    __shared__ float As[16][132];
    __shared__ float Bs[16][132];
    int tid = threadIdx.x;
    int m0 = blockIdx.y * 128, n0 = blockIdx.x * 128;
    int tx = tid & 15, ty = tid >> 4;
    int lrow = tid >> 1;           // 0..127
    int lk = (tid & 1) * 8;        // 0 or 8
    const float* Ap = A + (size_t)(m0 + lrow) * K + lk;
    const float* Bp = B + (size_t)(n0 + lrow) * K + lk;

    float acc[8][8];
#pragma unroll
    for (int i = 0; i < 8; i++)
#pragma unroll
        for (int j = 0; j < 8; j++) acc[i][j] = 0.f;

    for (int k0 = 0; k0 < K; k0 += 16) {
        float4 a0 = *(const float4*)(Ap + k0);
        float4 a1 = *(const float4*)(Ap + k0 + 4);
        float4 b0 = *(const float4*)(Bp + k0);
        float4 b1 = *(const float4*)(Bp + k0 + 4);
        __syncthreads();
        As[lk+0][lrow]=a0.x; As[lk+1][lrow]=a0.y; As[lk+2][lrow]=a0.z; As[lk+3][lrow]=a0.w;
        As[lk+4][lrow]=a1.x; As[lk+5][lrow]=a1.y; As[lk+6][lrow]=a1.z; As[lk+7][lrow]=a1.w;
        Bs[lk+0][lrow]=b0.x; Bs[lk+1][lrow]=b0.y; Bs[lk+2][lrow]=b0.z; Bs[lk+3][lrow]=b0.w;
        Bs[lk+4][lrow]=b1.x; Bs[lk+5][lrow]=b1.y; Bs[lk+6][lrow]=b1.z; Bs[lk+7][lrow]=b1.w;
        __syncthreads();
#pragma unroll
        for (int kk = 0; kk < 16; kk++) {
            float av[8], bv[8];
            *(float4*)(av)   = *(const float4*)&As[kk][ty*8];
            *(float4*)(av+4) = *(const float4*)&As[kk][ty*8+4];
            *(float4*)(bv)   = *(const float4*)&Bs[kk][tx*8];
            *(float4*)(bv+4) = *(const float4*)&Bs[kk][tx*8+4];
#pragma unroll
            for (int i = 0; i < 8; i++)
#pragma unroll
                for (int j = 0; j < 8; j++)
                    acc[i][j] = fmaf(av[i], bv[j], acc[i][j]);
        }
    }
#pragma unroll
    for (int i = 0; i < 8; i++) {
        float* cp = C + (size_t)(m0 + ty*8 + i) * N + n0 + tx*8;
        *(float4*)cp     = make_float4(acc[i][0], acc[i][1], acc[i][2], acc[i][3]);
        *(float4*)(cp+4) = make_float4(acc[i][4], acc[i][5], acc[i][6], acc[i][7]);
    }
}

// ---------------------------------------------------------------------------
// Landmarks: segment mean over 64 consecutive t.  grid (64 mi, 32 bh, 2), 64 thr
// ---------------------------------------------------------------------------
__global__ void landmark_kernel(const float* __restrict__ Q, const float* __restrict__ K,
                                float* __restrict__ Qlm, float* __restrict__ Klm)
{
    int mi = blockIdx.x, bh = blockIdx.y;
    int b = bh >> 4, h = bh & 15;
    const float* src = blockIdx.z ? K : Q;
    float* dst = blockIdx.z ? Klm : Qlm;
    int d = threadIdx.x;
    const float* p = src + ((size_t)b * T_SEQ + mi * 64) * DMODEL + h * 64 + d;
    float s = 0.f;
#pragma unroll 8
    for (int r = 0; r < 64; r++) s += p[(size_t)r * DMODEL];
    dst[((size_t)bh * 64 + mi) * 64 + d] = s * 0.015625f;
}

// ---------------------------------------------------------------------------
// scores: out[bh][t][mi] = (X_row(t) . Ylm[mi]) / 8, optional softmax over mi.
// grid (T/128, 32), 128 threads (one t per thread).
// ---------------------------------------------------------------------------
__global__ __launch_bounds__(128) void scores_kernel(
    const float* __restrict__ X, const float* __restrict__ Ylm,
    float* __restrict__ out, int do_softmax)
{
    int bh = blockIdx.y;
    int b = bh >> 4, h = bh & 15;
    int tid = threadIdx.x;
    int t = blockIdx.x * 128 + tid;
    __shared__ float4 Ks[1024];        // Ylm as [mi][d/4], 16 KB
    __shared__ float Ssc[64 * 128];    // [mi][tid], 32 KB
    const float4* Ysrc = (const float4*)(Ylm + (size_t)bh * 4096);
    for (int i = tid; i < 1024; i += 128) Ks[i] = Ysrc[i];
    __syncthreads();

    const float4* xrow = (const float4*)(X + ((size_t)b * T_SEQ + t) * DMODEL + h * 64);
    float q[64];
#pragma unroll
    for (int d4 = 0; d4 < 16; d4++) {
        float4 v = xrow[d4];
        q[4*d4+0]=v.x; q[4*d4+1]=v.y; q[4*d4+2]=v.z; q[4*d4+3]=v.w;
    }
    for (int mi = 0; mi < 64; mi++) {
        float acc = 0.f;
#pragma unroll
        for (int d4 = 0; d4 < 16; d4++) {
            float4 k4 = Ks[mi*16 + d4];
            acc = fmaf(q[4*d4+0], k4.x, acc);
            acc = fmaf(q[4*d4+1], k4.y, acc);
            acc = fmaf(q[4*d4+2], k4.z, acc);
            acc = fmaf(q[4*d4+3], k4.w, acc);
        }
        Ssc[mi*128 + tid] = acc * 0.125f;
    }
    float* orow = out + ((size_t)bh * T_SEQ + t) * 64;
    if (do_softmax) {
        float m = -INFINITY;
        for (int mi = 0; mi < 64; mi++) m = fmaxf(m, Ssc[mi*128 + tid]);
        float z = 0.f;
        for (int mi = 0; mi < 64; mi++) {
            float e = expf(Ssc[mi*128 + tid] - m);
            Ssc[mi*128 + tid] = e; z += e;
        }
        float inv = 1.0f / z;
        for (int mi = 0; mi < 64; mi += 4) {
            float4 o = make_float4(Ssc[(mi+0)*128+tid]*inv, Ssc[(mi+1)*128+tid]*inv,
                                   Ssc[(mi+2)*128+tid]*inv, Ssc[(mi+3)*128+tid]*inv);
            *(float4*)(orow + mi) = o;
        }
    } else {
        for (int mi = 0; mi < 64; mi += 4) {
            float4 o = make_float4(Ssc[(mi+0)*128+tid], Ssc[(mi+1)*128+tid],
                                   Ssc[(mi+2)*128+tid], Ssc[(mi+3)*128+tid]);
            *(float4*)(orow + mi) = o;
        }
    }
}

// ---------------------------------------------------------------------------
// Column softmax stats over t (per bh, mi): online max & sumexp.  grid 32, 256 thr
// ---------------------------------------------------------------------------
__global__ void colstats_kernel(const float* __restrict__ S,
                                float* __restrict__ cmax, float* __restrict__ csum)
{
    int bh = blockIdx.x;
    int tid = threadIdx.x;
    int mi = tid & 63, sub = tid >> 6;
    const float* base = S + (size_t)bh * T_SEQ * 64;
    float m = -INFINITY, z = 0.f;
    for (int t = sub; t < T_SEQ; t += 4) {
        float v = base[(size_t)t * 64 + mi];
        if (v > m) { z = z * expf(m - v) + 1.f; m = v; }
        else        z += expf(v - m);
    }
    __shared__ float sm[256], sz[256];
    sm[tid] = m; sz[tid] = z;
    __syncthreads();
    if (sub == 0) {
        for (int s2 = 1; s2 < 4; s2++) {
            float m2 = sm[s2*64 + mi], z2 = sz[s2*64 + mi];
            float nm = fmaxf(m, m2);
            z = z * expf(m - nm) + z2 * expf(m2 - nm);
            m = nm;
        }
        cmax[bh*64 + mi] = m;
        csum[bh*64 + mi] = z;
    }
}

// ---------------------------------------------------------------------------
// BV partials: part[bh][chunk] = sum over 512 t of exp(S - cmax) * V
// grid (8 chunks, 32 bh), 256 threads, 4x4 microtile.
// ---------------------------------------------------------------------------
__global__ __launch_bounds__(256) void bv_partial_kernel(
    const float* __restrict__ S, const float* __restrict__ V,
    const float* __restrict__ cmax, float* __restrict__ part)
{
    int chunk = blockIdx.x, bh = blockIdx.y;
    int b = bh >> 4, h = bh & 15;
    __shared__ float Es[64][65];
    __shared__ float Vs[64][65];
    __shared__ float cm[64];
    int tid = threadIdx.x;
    if (tid < 64) cm[tid] = cmax[bh*64 + tid];
    int ti = tid >> 4, tj = tid & 15;
    float acc[4][4] = {};
    for (int t0 = chunk*512; t0 < chunk*512 + 512; t0 += 64) {
        __syncthreads();
        for (int i = tid; i < 4096; i += 256) {
            int r = i >> 6, c = i & 63;
            Es[r][c] = expf(S[((size_t)bh*T_SEQ + t0 + r)*64 + c] - cm[c]);
            Vs[r][c] = V[((size_t)b*T_SEQ + t0 + r)*DMODEL + h*64 + c];
        }
        __syncthreads();
#pragma unroll 4
        for (int r = 0; r < 64; r++) {
            float a[4], bb[4];
#pragma unroll
            for (int x = 0; x < 4; x++) a[x]  = Es[r][ti*4+x];
#pragma unroll
            for (int y = 0; y < 4; y++) bb[y] = Vs[r][tj*4+y];
#pragma unroll
            for (int x = 0; x < 4; x++)
#pragma unroll
                for (int y = 0; y < 4; y++)
                    acc[x][y] = fmaf(a[x], bb[y], acc[x][y]);
        }
    }
    float* dst = part + ((size_t)(bh*8 + chunk)) * 4096;
#pragma unroll
    for (int x = 0; x < 4; x++)
#pragma unroll
        for (int y = 0; y < 4; y++)
            dst[(ti*4+x)*64 + tj*4+y] = acc[x][y];
}

__global__ void bv_reduce_kernel(const float* __restrict__ part,
                                 const float* __restrict__ csum, float* __restrict__ BV)
{
    int bh = blockIdx.x, tid = threadIdx.x;
    for (int i = tid; i < 4096; i += 256) {
        float s = 0.f;
#pragma unroll
        for (int ch = 0; ch < 8; ch++) s += part[((size_t)(bh*8 + ch))*4096 + i];
        BV[(size_t)bh*4096 + i] = s / csum[bh*64 + (i >> 6)];
    }
}

// ---------------------------------------------------------------------------
// Per-head: C_hat = rowsoftmax(Qlm Klm^T / 8); SVD via one-sided Jacobi;
// pinv with JAX cutoff (rcond = 10*64*eps); CBV = pinv(C) @ BV.
// grid 32, 256 threads, dynamic smem 50432 B.
// ---------------------------------------------------------------------------
__global__ __launch_bounds__(256) void pinv_cbv_kernel(
    const float* __restrict__ Qlm, const float* __restrict__ Klm,
    const float* __restrict__ BV, float* __restrict__ CBV)
{
    extern __shared__ float sp[];
    float* G    = sp;            // 64*65
    float* Vm   = sp + 4160;     // 64*65
    float* W    = sp + 8320;     // 64*65
    float* svec = sp + 12480;    // 64
    float* wvec = sp + 12544;    // 64
    int bh = blockIdx.x;
    int tid = threadIdx.x;
    int ti = tid >> 4, tj = tid & 15;

    // Phase 1: load Qlm -> Vm, Klm -> W (padded rows)
    for (int i = tid; i < 4096; i += 256) {
        int r = i >> 6, c = i & 63;
        Vm[r*65 + c] = Qlm[(size_t)bh*4096 + i];
        W [r*65 + c] = Klm[(size_t)bh*4096 + i];
    }
    __syncthreads();

    // Phase 2: C scores into G (4x4 microtile per thread)
    {
        float cacc[4][4] = {};
        for (int d = 0; d < 64; d++) {
            float qa[4], kb[4];
#pragma unroll
            for (int x = 0; x < 4; x++) qa[x] = Vm[(ti*4+x)*65 + d];
#pragma unroll
            for (int y = 0; y < 4; y++) kb[y] = W[(tj*4+y)*65 + d];
#pragma unroll
            for (int x = 0; x < 4; x++)
#pragma unroll
                for (int y = 0; y < 4; y++)
                    cacc[x][y] = fmaf(qa[x], kb[y], cacc[x][y]);
        }
        __syncthreads();
#pragma unroll
        for (int x = 0; x < 4; x++)
#pragma unroll
            for (int y = 0; y < 4; y++)
                G[(ti*4+x)*65 + tj*4+y] = cacc[x][y] * 0.125f;
    }
    __syncthreads();

    // Phase 3: row softmax of G
    if (tid < 64) {
        float mx = -INFINITY;
        for (int c = 0; c < 64; c++) mx = fmaxf(mx, G[tid*65 + c]);
        float z = 0.f;
        for (int c = 0; c < 64; c++) {
            float e = expf(G[tid*65 + c] - mx);
            G[tid*65 + c] = e; z += e;
        }
        float inv = 1.f / z;
        for (int c = 0; c < 64; c++) G[tid*65 + c] *= inv;
    }
    __syncthreads();

    // Phase 4: Vm = I
    for (int i = tid; i < 64*65; i += 256) Vm[i] = 0.f;
    __syncthreads();
    if (tid < 64) Vm[tid*65 + tid] = 1.f;
    __syncthreads();

    // Phase 5: one-sided Jacobi sweeps (round-robin tournament schedule)
    {
        int p = tid >> 3, lane = tid & 7;
        for (int sw = 0; sw < NSWEEP; sw++) {
            for (int r = 0; r < 63; r++) {
                int ci, cj;
                if (p == 0) { ci = 63; cj = r; }
                else { ci = (r + p) % 63; cj = (r - p + 63) % 63; }
                float aa = 0.f, bb = 0.f, gg = 0.f;
                for (int q = lane; q < 64; q += 8) {
                    float gi = G[q*65 + ci], gj = G[q*65 + cj];
                    aa = fmaf(gi, gi, aa);
                    bb = fmaf(gj, gj, bb);
                    gg = fmaf(gi, gj, gg);
                }
#pragma unroll
                for (int o = 4; o > 0; o >>= 1) {
                    aa += __shfl_xor_sync(0xffffffffu, aa, o);
                    bb += __shfl_xor_sync(0xffffffffu, bb, o);
                    gg += __shfl_xor_sync(0xffffffffu, gg, o);
                }
                float c_ = 1.f, s_ = 0.f;
                if (fabsf(gg) > 1e-30f) {
                    float zeta = (bb - aa) / (2.0f * gg);
                    float t = copysignf(1.0f, zeta) / (fabsf(zeta) + sqrtf(1.0f + zeta*zeta));
                    c_ = 1.0f / sqrtf(1.0f + t*t);
                    s_ = c_ * t;
                }
                if (s_ != 0.f) {
                    for (int q = lane; q < 64; q += 8) {
                        float gi = G[q*65 + ci], gj = G[q*65 + cj];
                        G[q*65 + ci] = c_*gi - s_*gj;
                        G[q*65 + cj] = s_*gi + c_*gj;
                        float vi = Vm[q*65 + ci], vj = Vm[q*65 + cj];
                        Vm[q*65 + ci] = c_*vi - s_*vj;
                        Vm[q*65 + cj] = s_*vi + c_*vj;
                    }
                }
                __syncthreads();
            }
        }
    }

    // Phase 6: singular values, JAX pinv cutoff
    if (tid < 64) {
        float ss = 0.f;
        for (int q = 0; q < 64; q++) { float g = G[q*65 + tid]; ss = fmaf(g, g, ss); }
        svec[tid] = sqrtf(ss);
    }
    __syncthreads();
    if (tid < 64) {
        float smax = 0.f;
        for (int c = 0; c < 64; c++) smax = fmaxf(smax, svec[c]);
        float cut = 7.62939453125e-5f * smax;   // 10*64*eps(fp32)
        float s = svec[tid];
        wvec[tid] = (s > cut) ? 1.0f / (s * s) : 0.0f;
    }
    __syncthreads();

    // Phase 7: T1 = diag(w) * G^T * BV   (BV staged into W)
    for (int i = tid; i < 4096; i += 256)
        W[(i >> 6)*65 + (i & 63)] = BV[(size_t)bh*4096 + i];
    __syncthreads();
    float t1[4][4] = {};
    for (int q = 0; q < 64; q++) {
        float a[4], bb[4];
#pragma unroll
        for (int x = 0; x < 4; x++) a[x]  = G[q*65 + ti*4+x];
#pragma unroll
        for (int y = 0; y < 4; y++) bb[y] = W[q*65 + tj*4+y];
#pragma unroll
        for (int x = 0; x < 4; x++)
#pragma unroll
            for (int y = 0; y < 4; y++)
                t1[x][y] = fmaf(a[x], bb[y], t1[x][y]);
    }
#pragma unroll
    for (int x = 0; x < 4; x++) {
        float w = wvec[ti*4+x];
#pragma unroll
        for (int y = 0; y < 4; y++) t1[x][y] *= w;
    }
    __syncthreads();
#pragma unroll
    for (int x = 0; x < 4; x++)
#pragma unroll
        for (int y = 0; y < 4; y++)
            G[(ti*4+x)*65 + tj*4+y] = t1[x][y];
    __syncthreads();

    // Phase 8: CBV = Vm @ T1
    float cb[4][4] = {};
    for (int q = 0; q < 64; q++) {
        float a[4], bb[4];
#pragma unroll
        for (int x = 0; x < 4; x++) a[x]  = Vm[(ti*4+x)*65 + q];
#pragma unroll
        for (int y = 0; y < 4; y++) bb[y] = G[q*65 + tj*4+y];
#pragma unroll
        for (int x = 0; x < 4; x++)
#pragma unroll
            for (int y = 0; y < 4; y++)
                cb[x][y] = fmaf(a[x], bb[y], cb[x][y]);
    }
#pragma unroll
    for (int x = 0; x < 4; x++)
#pragma unroll
        for (int y = 0; y < 4; y++)
            CBV[(size_t)bh*4096 + (ti*4+x)*64 + tj*4+y] = cb[x][y];
}

// ---------------------------------------------------------------------------
// Y = A_hat @ CBV per head, written into merged-head layout (B*T, 1024).
// grid (T/64, 32), 256 threads, 4x4 microtile.
// ---------------------------------------------------------------------------
__global__ __launch_bounds__(256) void av_kernel(
    const float* __restrict__ Ahat, const float* __restrict__ CBV,
    float* __restrict__ outp)
{
    int bh = blockIdx.y;
    int b = bh >> 4, h = bh & 15;
    int t0 = blockIdx.x * 64;
    __shared__ float As[64*65];  // [c][tl]  (A transposed)
    __shared__ float Cs[64*65];  // [c][d]
    int tid = threadIdx.x;
    for (int i = tid; i < 4096; i += 256) {
        int tl = i >> 6, c = i & 63;
        As[c*65 + tl] = Ahat[((size_t)bh*T_SEQ + t0 + tl)*64 + c];
        Cs[tl*65 + c] = CBV[(size_t)bh*4096 + i];
    }
    __syncthreads();
    int ti = tid >> 4, tj = tid & 15;
    float acc[4][4] = {};
    for (int c = 0; c < 64; c++) {
        float a[4], bb[4];
#pragma unroll
        for (int x = 0; x < 4; x++) a[x]  = As[c*65 + ti*4+x];
#pragma unroll
        for (int y = 0; y < 4; y++) bb[y] = Cs[c*65 + tj*4+y];
#pragma unroll
        for (int x = 0; x < 4; x++)
#pragma unroll
            for (int y = 0; y < 4; y++)
                acc[x][y] = fmaf(a[x], bb[y], acc[x][y]);
    }
#pragma unroll
    for (int x = 0; x < 4; x++) {
        float4 o = make_float4(acc[x][0], acc[x][1], acc[x][2], acc[x][3]);
        *(float4*)(outp + ((size_t)b*T_SEQ + t0 + ti*4 + x)*DMODEL + h*64 + tj*4) = o;
    }
}

// ---------------------------------------------------------------------------
extern "C" void kernel_launch(void* const* d_in, const int* in_sizes, int n_in,
                              void* d_out, int out_size)
{
    (void)in_sizes; (void)n_in; (void)out_size;
    const float* x  = (const float*)d_in[0];
    const float* Wq = (const float*)d_in[1];
    const float* Wk = (const float*)d_in[2];
    const float* Wv = (const float*)d_in[3];
    const float* Wo = (const float*)d_in[4];
    float* out = (float*)d_out;

    float *Q, *K, *V, *attn, *A, *S, *Qlm, *Klm, *BV, *CBV, *BVp, *cmax, *csum;
    cudaGetSymbolAddress((void**)&Q,    g_Q);
    cudaGetSymbolAddress((void**)&K,    g_K);
    cudaGetSymbolAddress((void**)&V,    g_V);
    cudaGetSymbolAddress((void**)&attn, g_attn);
    cudaGetSymbolAddress((void**)&A,    g_A);
    cudaGetSymbolAddress((void**)&S,    g_S);
    cudaGetSymbolAddress((void**)&Qlm,  g_Qlm);
    cudaGetSymbolAddress((void**)&Klm,  g_Klm);
    cudaGetSymbolAddress((void**)&BV,   g_BV);
    cudaGetSymbolAddress((void**)&CBV,  g_CBV);
    cudaGetSymbolAddress((void**)&BVp,  g_BVpart);
    cudaGetSymbolAddress((void**)&cmax, g_cmax);
    cudaGetSymbolAddress((void**)&csum, g_csum);

    cudaFuncSetAttribute(pinv_cbv_kernel,
                         cudaFuncAttributeMaxDynamicSharedMemorySize, 50432);

    dim3 gg(8, 64);  // (N/128, M/128)
    gemm_nt_kernel<<<gg, 256>>>(x, Wq, Q, NROWS, DMODEL, DMODEL);
    gemm_nt_kernel<<<gg, 256>>>(x, Wk, K, NROWS, DMODEL, DMODEL);
    gemm_nt_kernel<<<gg, 256>>>(x, Wv, V, NROWS, DMODEL, DMODEL);

    landmark_kernel<<<dim3(64, NBH, 2), 64>>>(Q, K, Qlm, Klm);

    scores_kernel<<<dim3(T_SEQ/128, NBH), 128>>>(Q, Klm, A, 1);  // A_hat
    scores_kernel<<<dim3(T_SEQ/128, NBH), 128>>>(K, Qlm, S, 0);  // B raw scores

    colstats_kernel<<<NBH, 256>>>(S, cmax, csum);
    bv_partial_kernel<<<dim3(8, NBH), 256>>>(S, V, cmax, BVp);
    bv_reduce_kernel<<<NBH, 256>>>(BVp, csum, BV);

    pinv_cbv_kernel<<<NBH, 256, 50432>>>(Qlm, Klm, BV, CBV);

    av_kernel<<<dim3(T_SEQ/64, NBH), 256>>>(A, CBV, attn);

    gemm_nt_kernel<<<gg, 256>>>(attn, Wo, out, NROWS, DMODEL, DMODEL);
}

// round 4
// speedup vs baseline: 1.4245x; 1.4245x over previous
#include <cuda_runtime.h>
#include <cuda_bf16.h>
#include <math.h>
#include <stdint.h>

// Problem constants: B=2, T=4096, d_model=1024, H=16, d_head=64, m=64
#define T_SEQ 4096
#define DMODEL 1024
#define NBH    32      // B*H
#define NROWS  8192    // B*T
#define NSWEEP 12

// ---------------- device scratch (no runtime allocation allowed) ----------------
__device__ __align__(16) float g_Q[NROWS * DMODEL];
__device__ __align__(16) float g_K[NROWS * DMODEL];
__device__ __align__(16) float g_V[NROWS * DMODEL];
__device__ __align__(16) float g_A[NBH * T_SEQ * 64];      // A_hat  [bh][t][mi]
__device__ __align__(16) float g_S[NBH * T_SEQ * 64];      // B raw scores
__device__ __align__(16) float g_Qlm[NBH * 64 * 64];
__device__ __align__(16) float g_Klm[NBH * 64 * 64];
__device__ __align__(16) float g_BV[NBH * 64 * 64];
__device__ __align__(16) float g_CBV[NBH * 64 * 64];
__device__ __align__(16) float g_BVpart[NBH * 8 * 64 * 64];
__device__ float g_cmax[NBH * 64];
__device__ float g_csum[NBH * 64];
// bf16 hi/lo splits
__device__ __align__(16) __nv_bfloat16 g_xh[NROWS * DMODEL];
__device__ __align__(16) __nv_bfloat16 g_xl[NROWS * DMODEL];
__device__ __align__(16) __nv_bfloat16 g_wh[4][DMODEL * DMODEL];
__device__ __align__(16) __nv_bfloat16 g_wl[4][DMODEL * DMODEL];
__device__ __align__(16) __nv_bfloat16 g_ah[NROWS * DMODEL];
__device__ __align__(16) __nv_bfloat16 g_al[NROWS * DMODEL];

// =====================  helpers  =====================
__device__ __forceinline__ uint32_t smem_u32(const void* p) {
    return (uint32_t)__cvta_generic_to_shared(p);
}
__device__ __forceinline__ void cp16(uint32_t dst, const void* src) {
    asm volatile("cp.async.cg.shared.global [%0], [%1], 16;" :: "r"(dst), "l"(src));
}
#define MMA16816(d, a, b) \
    asm volatile("mma.sync.aligned.m16n8k16.row.col.f32.bf16.bf16.f32 " \
        "{%0,%1,%2,%3},{%4,%5,%6,%7},{%8,%9},{%0,%1,%2,%3};" \
        : "+f"((d)[0]), "+f"((d)[1]), "+f"((d)[2]), "+f"((d)[3]) \
        : "r"((a)[0]), "r"((a)[1]), "r"((a)[2]), "r"((a)[3]), \
          "r"((b)[0]), "r"((b)[1]))

// ---------------------------------------------------------------------------
// split fp32 -> bf16 (hi, lo).
// ---------------------------------------------------------------------------
__global__ void split_kernel(const float4* __restrict__ in,
                             __nv_bfloat162* __restrict__ hi,
                             __nv_bfloat162* __restrict__ lo, int n4)
{
    int i = blockIdx.x * 256 + threadIdx.x;
    if (i >= n4) return;
    float4 v = in[i];
    __nv_bfloat16 h0 = __float2bfloat16(v.x);
    __nv_bfloat16 h1 = __float2bfloat16(v.y);
    __nv_bfloat16 h2 = __float2bfloat16(v.z);
    __nv_bfloat16 h3 = __float2bfloat16(v.w);
    __nv_bfloat162 H0, H1, L0, L1;
    H0.x = h0; H0.y = h1; H1.x = h2; H1.y = h3;
    L0.x = __float2bfloat16(v.x - __bfloat162float(h0));
    L0.y = __float2bfloat16(v.y - __bfloat162float(h1));
    L1.x = __float2bfloat16(v.z - __bfloat162float(h2));
    L1.y = __float2bfloat16(v.w - __bfloat162float(h3));
    hi[2*i] = H0; hi[2*i+1] = H1;
    lo[2*i] = L0; lo[2*i+1] = L1;
}

// ---------------------------------------------------------------------------
// mma.sync NT GEMM in 3xBF16 split precision:
//   C[M,N] = Ahi*Bhi^T + Ahi*Blo^T + Alo*Bhi^T   (fp32 accumulation)
// 128x128 CTA tile, 8 warps (warp tile 32x64), K-chunks of 32,
// 3-stage cp.async pipeline. SMEM rows padded to 80B (conflict-free frags).
// ---------------------------------------------------------------------------
#define GM_ROWB  80                 // bytes per smem row (32 bf16 + 8 pad)
#define GM_TILE  (128 * GM_ROWB)    // 10240 B
#define GM_STAGE (4 * GM_TILE)      // 40960 B (AH, AL, BH, BL)
#define GM_SMEM  (3 * GM_STAGE)     // 122880 B

__global__ __launch_bounds__(256, 1) void gemm_mma_kernel(
    const __nv_bfloat16* __restrict__ Ahi, const __nv_bfloat16* __restrict__ Alo,
    const __nv_bfloat16* __restrict__ Bhi, const __nv_bfloat16* __restrict__ Blo,
    float* __restrict__ C, int M, int N, int K)
{
    extern __shared__ __align__(128) char smem[];
    const int tid = threadIdx.x;
    const int m0 = blockIdx.y * 128, n0 = blockIdx.x * 128;
    const int wid = tid >> 5, lane = tid & 31;
    const int wr = (wid & 3) * 32;   // warp m offset in tile
    const int wc = (wid >> 2) * 64;  // warp n offset in tile
    const int lrow = tid >> 2;       // 0..63 (load row, +64 for i=1)
    const int lseg = tid & 3;        // 16B segment within 64B row data

    const int nchunks = K >> 5;      // K / 32

    auto load_stage = [&](int s, int kc) {
        uint32_t st = smem_u32(smem) + s * GM_STAGE;
#pragma unroll
        for (int i = 0; i < 2; i++) {
            int row = lrow + i * 64;
            uint32_t off = row * GM_ROWB + lseg * 16;
            const __nv_bfloat16* gA = Ahi + (size_t)(m0 + row) * K + kc + lseg * 8;
            const __nv_bfloat16* gAl = Alo + (size_t)(m0 + row) * K + kc + lseg * 8;
            const __nv_bfloat16* gB = Bhi + (size_t)(n0 + row) * K + kc + lseg * 8;
            const __nv_bfloat16* gBl = Blo + (size_t)(n0 + row) * K + kc + lseg * 8;
            cp16(st +             off, gA);
            cp16(st + GM_TILE   + off, gAl);
            cp16(st + 2*GM_TILE + off, gB);
            cp16(st + 3*GM_TILE + off, gBl);
        }
        asm volatile("cp.async.commit_group;" ::: "memory");
    };

    // prologue: fill 3 stages
    load_stage(0, 0);
    load_stage(1, 32);
    load_stage(2, 64);

    float acc[2][8][4];
#pragma unroll
    for (int mt = 0; mt < 2; mt++)
#pragma unroll
        for (int nt = 0; nt < 8; nt++)
#pragma unroll
            for (int q = 0; q < 4; q++) acc[mt][nt][q] = 0.f;

    const int fr = lane >> 2;        // fragment row within 8
    const int fc = (lane & 3) * 2;   // fragment col (k) within 8

    for (int c = 0; c < nchunks; c++) {
        int s = c % 3;
        asm volatile("cp.async.wait_group 2;" ::: "memory");
        __syncthreads();
        const char* st = smem + s * GM_STAGE;
        const char* tAH = st;
        const char* tAL = st + GM_TILE;
        const char* tBH = st + 2*GM_TILE;
        const char* tBL = st + 3*GM_TILE;

#pragma unroll
        for (int k16 = 0; k16 < 32; k16 += 16) {
            uint32_t aH[2][4], aL[2][4];
#pragma unroll
            for (int mt = 0; mt < 2; mt++) {
                int arow = wr + mt*16 + fr;
                int acol = k16 + fc;
                const char* pH = tAH + arow*GM_ROWB + acol*2;
                const char* pL = tAL + arow*GM_ROWB + acol*2;
                aH[mt][0] = *(const uint32_t*)(pH);
                aH[mt][1] = *(const uint32_t*)(pH + 8*GM_ROWB);
                aH[mt][2] = *(const uint32_t*)(pH + 16);
                aH[mt][3] = *(const uint32_t*)(pH + 8*GM_ROWB + 16);
                aL[mt][0] = *(const uint32_t*)(pL);
                aL[mt][1] = *(const uint32_t*)(pL + 8*GM_ROWB);
                aL[mt][2] = *(const uint32_t*)(pL + 16);
                aL[mt][3] = *(const uint32_t*)(pL + 8*GM_ROWB + 16);
            }
            uint32_t bH[8][2], bL[8][2];
#pragma unroll
            for (int nt = 0; nt < 8; nt++) {
                int brow = wc + nt*8 + fr;
                int bcol = k16 + fc;
                const char* pH = tBH + brow*GM_ROWB + bcol*2;
                const char* pL = tBL + brow*GM_ROWB + bcol*2;
                bH[nt][0] = *(const uint32_t*)(pH);
                bH[nt][1] = *(const uint32_t*)(pH + 16);
                bL[nt][0] = *(const uint32_t*)(pL);
                bL[nt][1] = *(const uint32_t*)(pL + 16);
            }
#pragma unroll
            for (int mt = 0; mt < 2; mt++)
#pragma unroll
                for (int nt = 0; nt < 8; nt++)
                    MMA16816(acc[mt][nt], aH[mt], bH[nt]);
#pragma unroll
            for (int mt = 0; mt < 2; mt++)
#pragma unroll
                for (int nt = 0; nt < 8; nt++)
                    MMA16816(acc[mt][nt], aH[mt], bL[nt]);
#pragma unroll
            for (int mt = 0; mt < 2; mt++)
#pragma unroll
                for (int nt = 0; nt < 8; nt++)
                    MMA16816(acc[mt][nt], aL[mt], bH[nt]);
        }
        __syncthreads();
        if (c + 3 < nchunks) {
            load_stage(s, (c + 3) * 32);
        } else {
            asm volatile("cp.async.commit_group;" ::: "memory");
        }
    }

    // epilogue
#pragma unroll
    for (int mt = 0; mt < 2; mt++) {
#pragma unroll
        for (int nt = 0; nt < 8; nt++) {
            int row = m0 + wr + mt*16 + fr;
            int col = n0 + wc + nt*8 + fc;
            *(float2*)(C + (size_t)row * N + col) =
                make_float2(acc[mt][nt][0], acc[mt][nt][1]);
            *(float2*)(C + (size_t)(row + 8) * N + col) =
                make_float2(acc[mt][nt][2], acc[mt][nt][3]);
        }
    }
}

// ---------------------------------------------------------------------------
// Landmarks: segment mean over 64 consecutive t.
// ---------------------------------------------------------------------------
__global__ void landmark_kernel(const float* __restrict__ Q, const float* __restrict__ K,
                                float* __restrict__ Qlm, float* __restrict__ Klm)
{
    int mi = blockIdx.x, bh = blockIdx.y;
    int b = bh >> 4, h = bh & 15;
    const float* src = blockIdx.z ? K : Q;
    float* dst = blockIdx.z ? Klm : Qlm;
    int d = threadIdx.x;
    const float* p = src + ((size_t)b * T_SEQ + mi * 64) * DMODEL + h * 64 + d;
    float s = 0.f;
#pragma unroll 8
    for (int r = 0; r < 64; r++) s += p[(size_t)r * DMODEL];
    dst[((size_t)bh * 64 + mi) * 64 + d] = s * 0.015625f;
}

// ---------------------------------------------------------------------------
// scores: out[bh][t][mi] = (X_row(t) . Ylm[mi]) / 8, optional softmax over mi.
// ---------------------------------------------------------------------------
__global__ __launch_bounds__(128) void scores_kernel(
    const float* __restrict__ X, const float* __restrict__ Ylm,
    float* __restrict__ out, int do_softmax)
{
    int bh = blockIdx.y;
    int b = bh >> 4, h = bh & 15;
    int tid = threadIdx.x;
    int t = blockIdx.x * 128 + tid;
    __shared__ float4 Ks[1024];
    __shared__ float Ssc[64 * 128];
    const float4* Ysrc = (const float4*)(Ylm + (size_t)bh * 4096);
    for (int i = tid; i < 1024; i += 128) Ks[i] = Ysrc[i];
    __syncthreads();

    const float4* xrow = (const float4*)(X + ((size_t)b * T_SEQ + t) * DMODEL + h * 64);
    float q[64];
#pragma unroll
    for (int d4 = 0; d4 < 16; d4++) {
        float4 v = xrow[d4];
        q[4*d4+0]=v.x; q[4*d4+1]=v.y; q[4*d4+2]=v.z; q[4*d4+3]=v.w;
    }
    for (int mi = 0; mi < 64; mi++) {
        float acc = 0.f;
#pragma unroll
        for (int d4 = 0; d4 < 16; d4++) {
            float4 k4 = Ks[mi*16 + d4];
            acc = fmaf(q[4*d4+0], k4.x, acc);
            acc = fmaf(q[4*d4+1], k4.y, acc);
            acc = fmaf(q[4*d4+2], k4.z, acc);
            acc = fmaf(q[4*d4+3], k4.w, acc);
        }
        Ssc[mi*128 + tid] = acc * 0.125f;
    }
    float* orow = out + ((size_t)bh * T_SEQ + t) * 64;
    if (do_softmax) {
        float m = -INFINITY;
        for (int mi = 0; mi < 64; mi++) m = fmaxf(m, Ssc[mi*128 + tid]);
        float z = 0.f;
        for (int mi = 0; mi < 64; mi++) {
            float e = expf(Ssc[mi*128 + tid] - m);
            Ssc[mi*128 + tid] = e; z += e;
        }
        float inv = 1.0f / z;
        for (int mi = 0; mi < 64; mi += 4) {
            float4 o = make_float4(Ssc[(mi+0)*128+tid]*inv, Ssc[(mi+1)*128+tid]*inv,
                                   Ssc[(mi+2)*128+tid]*inv, Ssc[(mi+3)*128+tid]*inv);
            *(float4*)(orow + mi) = o;
        }
    } else {
        for (int mi = 0; mi < 64; mi += 4) {
            float4 o = make_float4(Ssc[(mi+0)*128+tid], Ssc[(mi+1)*128+tid],
                                   Ssc[(mi+2)*128+tid], Ssc[(mi+3)*128+tid]);
            *(float4*)(orow + mi) = o;
        }
    }
}

// ---------------------------------------------------------------------------
__global__ void colstats_kernel(const float* __restrict__ S,
                                float* __restrict__ cmax, float* __restrict__ csum)
{
    int bh = blockIdx.x;
    int tid = threadIdx.x;
    int mi = tid & 63, sub = tid >> 6;
    const float* base = S + (size_t)bh * T_SEQ * 64;
    float m = -INFINITY, z = 0.f;
    for (int t = sub; t < T_SEQ; t += 4) {
        float v = base[(size_t)t * 64 + mi];
        if (v > m) { z = z * expf(m - v) + 1.f; m = v; }
        else        z += expf(v - m);
    }
    __shared__ float sm[256], sz[256];
    sm[tid] = m; sz[tid] = z;
    __syncthreads();
    if (sub == 0) {
        for (int s2 = 1; s2 < 4; s2++) {
            float m2 = sm[s2*64 + mi], z2 = sz[s2*64 + mi];
            float nm = fmaxf(m, m2);
            z = z * expf(m - nm) + z2 * expf(m2 - nm);
            m = nm;
        }
        cmax[bh*64 + mi] = m;
        csum[bh*64 + mi] = z;
    }
}

// ---------------------------------------------------------------------------
__global__ __launch_bounds__(256) void bv_partial_kernel(
    const float* __restrict__ S, const float* __restrict__ V,
    const float* __restrict__ cmax, float* __restrict__ part)
{
    int chunk = blockIdx.x, bh = blockIdx.y;
    int b = bh >> 4, h = bh & 15;
    __shared__ float Es[64][65];
    __shared__ float Vs[64][65];
    __shared__ float cm[64];
    int tid = threadIdx.x;
    if (tid < 64) cm[tid] = cmax[bh*64 + tid];
    int ti = tid >> 4, tj = tid & 15;
    float acc[4][4] = {};
    for (int t0 = chunk*512; t0 < chunk*512 + 512; t0 += 64) {
        __syncthreads();
        for (int i = tid; i < 4096; i += 256) {
            int r = i >> 6, c = i & 63;
            Es[r][c] = expf(S[((size_t)bh*T_SEQ + t0 + r)*64 + c] - cm[c]);
            Vs[r][c] = V[((size_t)b*T_SEQ + t0 + r)*DMODEL + h*64 + c];
        }
        __syncthreads();
#pragma unroll 4
        for (int r = 0; r < 64; r++) {
            float a[4], bb[4];
#pragma unroll
            for (int x = 0; x < 4; x++) a[x]  = Es[r][ti*4+x];
#pragma unroll
            for (int y = 0; y < 4; y++) bb[y] = Vs[r][tj*4+y];
#pragma unroll
            for (int x = 0; x < 4; x++)
#pragma unroll
                for (int y = 0; y < 4; y++)
                    acc[x][y] = fmaf(a[x], bb[y], acc[x][y]);
        }
    }
    float* dst = part + ((size_t)(bh*8 + chunk)) * 4096;
#pragma unroll
    for (int x = 0; x < 4; x++)
#pragma unroll
        for (int y = 0; y < 4; y++)
            dst[(ti*4+x)*64 + tj*4+y] = acc[x][y];
}

__global__ void bv_reduce_kernel(const float* __restrict__ part,
                                 const float* __restrict__ csum, float* __restrict__ BV)
{
    int bh = blockIdx.x, tid = threadIdx.x;
    for (int i = tid; i < 4096; i += 256) {
        float s = 0.f;
#pragma unroll
        for (int ch = 0; ch < 8; ch++) s += part[((size_t)(bh*8 + ch))*4096 + i];
        BV[(size_t)bh*4096 + i] = s / csum[bh*64 + (i >> 6)];
    }
}

// ---------------------------------------------------------------------------
// pinv(C_hat) @ BV via one-sided Jacobi SVD, JAX cutoff rcond=10*64*eps.
// ---------------------------------------------------------------------------
__global__ __launch_bounds__(256) void pinv_cbv_kernel(
    const float* __restrict__ Qlm, const float* __restrict__ Klm,
    const float* __restrict__ BV, float* __restrict__ CBV)
{
    extern __shared__ float sp[];
    float* G    = sp;
    float* Vm   = sp + 4160;
    float* W    = sp + 8320;
    float* svec = sp + 12480;
    float* wvec = sp + 12544;
    int bh = blockIdx.x;
    int tid = threadIdx.x;
    int ti = tid >> 4, tj = tid & 15;

    for (int i = tid; i < 4096; i += 256) {
        int r = i >> 6, c = i & 63;
        Vm[r*65 + c] = Qlm[(size_t)bh*4096 + i];
        W [r*65 + c] = Klm[(size_t)bh*4096 + i];
    }
    __syncthreads();

    {
        float cacc[4][4] = {};
        for (int d = 0; d < 64; d++) {
            float qa[4], kb[4];
#pragma unroll
            for (int x = 0; x < 4; x++) qa[x] = Vm[(ti*4+x)*65 + d];
#pragma unroll
            for (int y = 0; y < 4; y++) kb[y] = W[(tj*4+y)*65 + d];
#pragma unroll
            for (int x = 0; x < 4; x++)
#pragma unroll
                for (int y = 0; y < 4; y++)
                    cacc[x][y] = fmaf(qa[x], kb[y], cacc[x][y]);
        }
        __syncthreads();
#pragma unroll
        for (int x = 0; x < 4; x++)
#pragma unroll
            for (int y = 0; y < 4; y++)
                G[(ti*4+x)*65 + tj*4+y] = cacc[x][y] * 0.125f;
    }
    __syncthreads();

    if (tid < 64) {
        float mx = -INFINITY;
        for (int c = 0; c < 64; c++) mx = fmaxf(mx, G[tid*65 + c]);
        float z = 0.f;
        for (int c = 0; c < 64; c++) {
            float e = expf(G[tid*65 + c] - mx);
            G[tid*65 + c] = e; z += e;
        }
        float inv = 1.f / z;
        for (int c = 0; c < 64; c++) G[tid*65 + c] *= inv;
    }
    __syncthreads();

    for (int i = tid; i < 64*65; i += 256) Vm[i] = 0.f;
    __syncthreads();
    if (tid < 64) Vm[tid*65 + tid] = 1.f;
    __syncthreads();

    {
        int p = tid >> 3, lane = tid & 7;
        for (int sw = 0; sw < NSWEEP; sw++) {
            for (int r = 0; r < 63; r++) {
                int ci, cj;
                if (p == 0) { ci = 63; cj = r; }
                else { ci = (r + p) % 63; cj = (r - p + 63) % 63; }
                float aa = 0.f, bb = 0.f, gg = 0.f;
                for (int q = lane; q < 64; q += 8) {
                    float gi = G[q*65 + ci], gj = G[q*65 + cj];
                    aa = fmaf(gi, gi, aa);
                    bb = fmaf(gj, gj, bb);
                    gg = fmaf(gi, gj, gg);
                }
#pragma unroll
                for (int o = 4; o > 0; o >>= 1) {
                    aa += __shfl_xor_sync(0xffffffffu, aa, o);
                    bb += __shfl_xor_sync(0xffffffffu, bb, o);
                    gg += __shfl_xor_sync(0xffffffffu, gg, o);
                }
                float c_ = 1.f, s_ = 0.f;
                if (fabsf(gg) > 1e-30f) {
                    float zeta = (bb - aa) / (2.0f * gg);
                    float t = copysignf(1.0f, zeta) / (fabsf(zeta) + sqrtf(1.0f + zeta*zeta));
                    c_ = 1.0f / sqrtf(1.0f + t*t);
                    s_ = c_ * t;
                }
                if (s_ != 0.f) {
                    for (int q = lane; q < 64; q += 8) {
                        float gi = G[q*65 + ci], gj = G[q*65 + cj];
                        G[q*65 + ci] = c_*gi - s_*gj;
                        G[q*65 + cj] = s_*gi + c_*gj;
                        float vi = Vm[q*65 + ci], vj = Vm[q*65 + cj];
                        Vm[q*65 + ci] = c_*vi - s_*vj;
                        Vm[q*65 + cj] = s_*vi + c_*vj;
                    }
                }
                __syncthreads();
            }
        }
    }

    if (tid < 64) {
        float ss = 0.f;
        for (int q = 0; q < 64; q++) { float g = G[q*65 + tid]; ss = fmaf(g, g, ss); }
        svec[tid] = sqrtf(ss);
    }
    __syncthreads();
    if (tid < 64) {
        float smax = 0.f;
        for (int c = 0; c < 64; c++) smax = fmaxf(smax, svec[c]);
        float cut = 7.62939453125e-5f * smax;
        float s = svec[tid];
        wvec[tid] = (s > cut) ? 1.0f / (s * s) : 0.0f;
    }
    __syncthreads();

    for (int i = tid; i < 4096; i += 256)
        W[(i >> 6)*65 + (i & 63)] = BV[(size_t)bh*4096 + i];
    __syncthreads();
    float t1[4][4] = {};
    for (int q = 0; q < 64; q++) {
        float a[4], bb[4];
#pragma unroll
        for (int x = 0; x < 4; x++) a[x]  = G[q*65 + ti*4+x];
#pragma unroll
        for (int y = 0; y < 4; y++) bb[y] = W[q*65 + tj*4+y];
#pragma unroll
        for (int x = 0; x < 4; x++)
#pragma unroll
            for (int y = 0; y < 4; y++)
                t1[x][y] = fmaf(a[x], bb[y], t1[x][y]);
    }
#pragma unroll
    for (int x = 0; x < 4; x++) {
        float w = wvec[ti*4+x];
#pragma unroll
        for (int y = 0; y < 4; y++) t1[x][y] *= w;
    }
    __syncthreads();
#pragma unroll
    for (int x = 0; x < 4; x++)
#pragma unroll
        for (int y = 0; y < 4; y++)
            G[(ti*4+x)*65 + tj*4+y] = t1[x][y];
    __syncthreads();

    float cb[4][4] = {};
    for (int q = 0; q < 64; q++) {
        float a[4], bb[4];
#pragma unroll
        for (int x = 0; x < 4; x++) a[x]  = Vm[(ti*4+x)*65 + q];
#pragma unroll
        for (int y = 0; y < 4; y++) bb[y] = G[q*65 + tj*4+y];
#pragma unroll
        for (int x = 0; x < 4; x++)
#pragma unroll
            for (int y = 0; y < 4; y++)
                cb[x][y] = fmaf(a[x], bb[y], cb[x][y]);
    }
#pragma unroll
    for (int x = 0; x < 4; x++)
#pragma unroll
        for (int y = 0; y < 4; y++)
            CBV[(size_t)bh*4096 + (ti*4+x)*64 + tj*4+y] = cb[x][y];
}

// ---------------------------------------------------------------------------
// Y = A_hat @ CBV per head -> bf16 hi/lo splits in merged-head layout.
// ---------------------------------------------------------------------------
__global__ __launch_bounds__(256) void av_kernel(
    const float* __restrict__ Ahat, const float* __restrict__ CBV,
    __nv_bfloat16* __restrict__ ahp, __nv_bfloat16* __restrict__ alp)
{
    int bh = blockIdx.y;
    int b = bh >> 4, hh = bh & 15;
    int t0 = blockIdx.x * 64;
    __shared__ float As[64*65];
    __shared__ float Cs[64*65];
    int tid = threadIdx.x;
    for (int i = tid; i < 4096; i += 256) {
        int tl = i >> 6, c = i & 63;
        As[c*65 + tl] = Ahat[((size_t)bh*T_SEQ + t0 + tl)*64 + c];
        Cs[tl*65 + c] = CBV[(size_t)bh*4096 + i];
    }
    __syncthreads();
    int ti = tid >> 4, tj = tid & 15;
    float acc[4][4] = {};
    for (int c = 0; c < 64; c++) {
        float a[4], bb[4];
#pragma unroll
        for (int x = 0; x < 4; x++) a[x]  = As[c*65 + ti*4+x];
#pragma unroll
        for (int y = 0; y < 4; y++) bb[y] = Cs[c*65 + tj*4+y];
#pragma unroll
        for (int x = 0; x < 4; x++)
#pragma unroll
            for (int y = 0; y < 4; y++)
                acc[x][y] = fmaf(a[x], bb[y], acc[x][y]);
    }
#pragma unroll
    for (int x = 0; x < 4; x++) {
        size_t idx = ((size_t)b*T_SEQ + t0 + ti*4 + x)*DMODEL + hh*64 + tj*4;
#pragma unroll
        for (int y = 0; y < 4; y += 2) {
            float v0 = acc[x][y], v1 = acc[x][y+1];
            __nv_bfloat16 h0 = __float2bfloat16(v0);
            __nv_bfloat16 h1 = __float2bfloat16(v1);
            __nv_bfloat162 Hp, Lp;
            Hp.x = h0; Hp.y = h1;
            Lp.x = __float2bfloat16(v0 - __bfloat162float(h0));
            Lp.y = __float2bfloat16(v1 - __bfloat162float(h1));
            *(__nv_bfloat162*)(ahp + idx + y) = Hp;
            *(__nv_bfloat162*)(alp + idx + y) = Lp;
        }
    }
}

// ---------------------------------------------------------------------------
extern "C" void kernel_launch(void* const* d_in, const int* in_sizes, int n_in,
                              void* d_out, int out_size)
{
    (void)in_sizes; (void)n_in; (void)out_size;
    const float* x = (const float*)d_in[0];
    const float* Wmat[4] = { (const float*)d_in[1], (const float*)d_in[2],
                             (const float*)d_in[3], (const float*)d_in[4] };
    float* out = (float*)d_out;

    float *Q, *K, *V, *A, *S, *Qlm, *Klm, *BV, *CBV, *BVp, *cmax, *csum;
    __nv_bfloat16 *xh, *xl, *wh, *wl, *ah, *al;
    cudaGetSymbolAddress((void**)&Q,    g_Q);
    cudaGetSymbolAddress((void**)&K,    g_K);
    cudaGetSymbolAddress((void**)&V,    g_V);
    cudaGetSymbolAddress((void**)&A,    g_A);
    cudaGetSymbolAddress((void**)&S,    g_S);
    cudaGetSymbolAddress((void**)&Qlm,  g_Qlm);
    cudaGetSymbolAddress((void**)&Klm,  g_Klm);
    cudaGetSymbolAddress((void**)&BV,   g_BV);
    cudaGetSymbolAddress((void**)&CBV,  g_CBV);
    cudaGetSymbolAddress((void**)&BVp,  g_BVpart);
    cudaGetSymbolAddress((void**)&cmax, g_cmax);
    cudaGetSymbolAddress((void**)&csum, g_csum);
    cudaGetSymbolAddress((void**)&xh,   g_xh);
    cudaGetSymbolAddress((void**)&xl,   g_xl);
    cudaGetSymbolAddress((void**)&wh,   g_wh);
    cudaGetSymbolAddress((void**)&wl,   g_wl);
    cudaGetSymbolAddress((void**)&ah,   g_ah);
    cudaGetSymbolAddress((void**)&al,   g_al);

    cudaFuncSetAttribute(pinv_cbv_kernel,
                         cudaFuncAttributeMaxDynamicSharedMemorySize, 50432);
    cudaFuncSetAttribute(gemm_mma_kernel,
                         cudaFuncAttributeMaxDynamicSharedMemorySize, GM_SMEM);

    // splits
    split_kernel<<<NROWS*DMODEL/4/256, 256>>>((const float4*)x,
        (__nv_bfloat162*)xh, (__nv_bfloat162*)xl, NROWS*DMODEL/4);
    for (int w = 0; w < 4; w++) {
        split_kernel<<<DMODEL*DMODEL/4/256, 256>>>((const float4*)Wmat[w],
            (__nv_bfloat162*)(wh + (size_t)w*DMODEL*DMODEL),
            (__nv_bfloat162*)(wl + (size_t)w*DMODEL*DMODEL), DMODEL*DMODEL/4);
    }

    dim3 gg(DMODEL/128, NROWS/128);   // (8, 64)
    gemm_mma_kernel<<<gg, 256, GM_SMEM>>>(xh, xl, wh + 0*(size_t)DMODEL*DMODEL,
                                          wl + 0*(size_t)DMODEL*DMODEL, Q, NROWS, DMODEL, DMODEL);
    gemm_mma_kernel<<<gg, 256, GM_SMEM>>>(xh, xl, wh + 1*(size_t)DMODEL*DMODEL,
                                          wl + 1*(size_t)DMODEL*DMODEL, K, NROWS, DMODEL, DMODEL);
    gemm_mma_kernel<<<gg, 256, GM_SMEM>>>(xh, xl, wh + 2*(size_t)DMODEL*DMODEL,
                                          wl + 2*(size_t)DMODEL*DMODEL, V, NROWS, DMODEL, DMODEL);

    landmark_kernel<<<dim3(64, NBH, 2), 64>>>(Q, K, Qlm, Klm);
    scores_kernel<<<dim3(T_SEQ/128, NBH), 128>>>(Q, Klm, A, 1);
    scores_kernel<<<dim3(T_SEQ/128, NBH), 128>>>(K, Qlm, S, 0);
    colstats_kernel<<<NBH, 256>>>(S, cmax, csum);
    bv_partial_kernel<<<dim3(8, NBH), 256>>>(S, V, cmax, BVp);
    bv_reduce_kernel<<<NBH, 256>>>(BVp, csum, BV);
    pinv_cbv_kernel<<<NBH, 256, 50432>>>(Qlm, Klm, BV, CBV);
    av_kernel<<<dim3(T_SEQ/64, NBH), 256>>>(A, CBV, ah, al);

    gemm_mma_kernel<<<gg, 256, GM_SMEM>>>(ah, al, wh + 3*(size_t)DMODEL*DMODEL,
                                          wl + 3*(size_t)DMODEL*DMODEL, out, NROWS, DMODEL, DMODEL);
}